// round 9
// baseline (speedup 1.0000x reference)
#include <cuda_runtime.h>

#define THETA 0.9999f
typedef unsigned long long ull;

__device__ __forceinline__ ull pk2(float x, float y) {
    ull r; asm("mov.b64 %0, {%1, %2};" : "=l"(r) : "f"(x), "f"(y)); return r;
}
__device__ __forceinline__ void upk2(float& x, float& y, ull v) {
    asm("mov.b64 {%0, %1}, %2;" : "=f"(x), "=f"(y) : "l"(v));
}
__device__ __forceinline__ ull fma2(ull a, ull b, ull c) {
    ull d; asm("fma.rn.f32x2 %0, %1, %2, %3;" : "=l"(d) : "l"(a), "l"(b), "l"(c)); return d;
}

// IF-neuron spike rate over 50 steps, constant drive a, soft reset.
// Closed form floor(50*a/theta); exact f32 sim only near count boundaries.
__device__ __forceinline__ float rate50(float a) {
    if (a <= 0.0f) return 0.0f;
    if (a >= THETA) return 1.0f;
    float u = a * (50.0f / THETA);
    float k = floorf(u);
    float d = u - k;
    if (d > 1e-4f && d < 0.9999f) {
        return k * 0.02f;
    }
    float v = 0.0f, cnt = 0.0f;
    #pragma unroll
    for (int t = 0; t < 50; ++t) {
        v += a;
        if (v >= THETA) { v -= THETA; cnt += 1.0f; }
    }
    return cnt * 0.02f;
}

// Shared layout (floats):
//   A  [0,184)      : mx (data at h+1); A[0..32) reused as reduction scratch
//   B1 [184,3256)   : r1 main (16 x stride 184, data at h+1), then r3 main (32 x stride 96, data at h+1)
//   B2 [3256,6328)  : r1 shadow (data at h), then r3 shadow (data at h)
//   C  [6328,11960) : r2 (32 x stride 176), then r4 (32 x stride 88)
#define SM_TOTAL 11960
#define B1_OFF 184
#define B2_OFF 3256
#define C_OFF  6328

// Packed conv + rate. Output pair (j,j+1), j even: even taps k read aligned
// pairs from main copy (win[j+k],win[j+k+1]); odd taps read aligned pairs from
// the shadow copy (shifted by one), so ONE packed accumulator set handles all
// taps. h0 must be even. Out-of-range outputs are computed on finite garbage
// and discarded by the store guard.
template<int NPAIR, int K, int NCH>
__device__ __forceinline__ void conv_packed(
    const float* __restrict__ Bm, const float* __restrict__ Bs,
    float* __restrict__ Cout,
    const float* __restrict__ w, const float* __restrict__ b,
    int in_stride, int out_stride, int lo, int hi, int tid)
{
    int o = tid >> 3;
    int h0 = lo + (tid & 7) * (2 * NPAIR);
    ull acc[NPAIR];
    float bb = b[o];
    ull bb2 = pk2(bb, bb);
    #pragma unroll
    for (int m = 0; m < NPAIR; ++m) acc[m] = bb2;
    for (int c = 0; c < NCH; ++c) {
        const ull* M2 = (const ull*)(Bm + c * in_stride + h0);
        const ull* S2 = (const ull*)(Bs + c * in_stride + h0);
        const float* wp = w + (o * NCH + c) * K;
        #pragma unroll
        for (int k = 0; k < K; k += 2) {      // even taps from main
            ull wv2 = pk2(wp[k], wp[k]);
            #pragma unroll
            for (int m = 0; m < NPAIR; ++m)
                acc[m] = fma2(M2[m + (k >> 1)], wv2, acc[m]);
        }
        #pragma unroll
        for (int k = 1; k < K; k += 2) {      // odd taps from shadow
            ull wv2 = pk2(wp[k], wp[k]);
            #pragma unroll
            for (int m = 0; m < NPAIR; ++m)
                acc[m] = fma2(S2[m + (k >> 1)], wv2, acc[m]);
        }
    }
    #pragma unroll
    for (int m = 0; m < NPAIR; ++m) {
        float a0, a1; upk2(a0, a1, acc[m]);
        int h = h0 + 2 * m;
        if (h < hi)     Cout[o * out_stride + h]     = rate50(a0);
        if (h + 1 < hi) Cout[o * out_stride + h + 1] = rate50(a1);
    }
}

__global__ void zero_out_kernel(float* __restrict__ out, int n) {
    int i = blockIdx.x * blockDim.x + threadIdx.x;
    if (i < n) out[i] = 0.0f;
}

__global__ __launch_bounds__(256, 4)
void catnet_kernel(const float* __restrict__ x,
                   const float* __restrict__ w1, const float* __restrict__ b1,
                   const float* __restrict__ w2, const float* __restrict__ b2,
                   const float* __restrict__ w3, const float* __restrict__ b3,
                   const float* __restrict__ wf, const float* __restrict__ bf,
                   float* __restrict__ out) {
    __shared__ float sm[SM_TOTAL];
    float* A  = sm;
    float* B1 = sm + B1_OFF;
    float* B2 = sm + B2_OFF;
    float* C  = sm + C_OFF;
    const int tid = threadIdx.x;
    const int n = blockIdx.x >> 1;
    const int half = blockIdx.x & 1;

    // zero all shared (establishes every pad cell in both copies)
    for (int i = tid; i < SM_TOTAL; i += 256) sm[i] = 0.0f;
    __syncthreads();

    // per-half stage ranges (global h)
    const int mx_lo = half ? 84 : 0,  mx_w = half ? 96 : 106;
    const int r1_lo = half ? 85 : 0,  r1_w = half ? 95 : 105;

    // ---- stage 0: mean over time -> A[h+1] ----
    const float2* xn2 = (const float2*)(x + (long)n * (180 * 50));
    if (tid < mx_w) {
        int h = mx_lo + tid;
        const float2* xp = xn2 + h * 25;
        float s0 = 0.0f, s1 = 0.0f;
        #pragma unroll
        for (int t = 0; t < 25; ++t) {
            float2 v = xp[t];
            s0 += v.x; s1 += v.y;
        }
        A[h + 1] = (s0 + s1) / 50.0f;
    }
    __syncthreads();

    // ---- stage 1: conv (16,1,3) pad 1 + rate -> r1 (main + shadow) ----
    for (int idx = tid; idx < 16 * r1_w; idx += 256) {
        int o = idx / r1_w, h = r1_lo + idx - o * r1_w;
        float a = b1[o]
                + A[h]     * w1[o * 3]
                + A[h + 1] * w1[o * 3 + 1]
                + A[h + 2] * w1[o * 3 + 2];
        float v = rate50(a);
        B1[o * 184 + h + 1] = v;
        B2[o * 184 + h]     = v;
    }
    __syncthreads();

    // ---- stage 2: conv (32,16,9) pad 1 + rate -> r2 in C (stride 176) ----
    if (half == 0)
        conv_packed<7, 9, 16>(B1, B2, C, w2, b2, 184, 176, 0, 98, tid);
    else
        conv_packed<6, 9, 16>(B1, B2, C, w2, b2, 184, 176, 86, 174, tid);
    __syncthreads();

    // ---- stage 3: sum-pool(2)*1.1 + rate -> r3 (main stride 96 at h+1, shadow at h) ----
    {
        const int r3_lo = half ? 43 : 0;
        const int r3_w  = half ? 44 : 49;
        for (int idx = tid; idx < 32 * r3_w; idx += 256) {
            int o = idx / r3_w, h = r3_lo + idx - o * r3_w;
            float a = 1.1f * (C[o * 176 + 2 * h] + C[o * 176 + 2 * h + 1]);
            float v = rate50(a);
            B1[o * 96 + h + 1] = v;
            B2[o * 96 + h]     = v;
        }
    }
    __syncthreads();
    // zero r3 pad cells in both copies (regions previously held r1 data);
    // zero reduction scratch (mx dead)
    if (tid < 32) {
        B1[tid * 96] = 0.0f;
        #pragma unroll
        for (int j = 88; j < 96; ++j) B1[tid * 96 + j] = 0.0f;
        #pragma unroll
        for (int j = 87; j < 96; ++j) B2[tid * 96 + j] = 0.0f;
        A[tid] = 0.0f;
    }
    __syncthreads();

    // ---- stage 4: conv (32,32,7) pad 1 + rate -> r4 in C (stride 88) ----
    if (half == 0)
        conv_packed<3, 7, 32>(B1, B2, C, w3, b3, 96, 88, 0, 44, tid);
    else
        conv_packed<3, 7, 32>(B1, B2, C, w3, b3, 96, 88, 44, 83, tid);
    __syncthreads();

    // ---- stage 5: dense partial over this half's r4 h-range ----
    {
        const int d_lo = half ? 44 : 0;
        const int d_w  = half ? 39 : 44;
        float p0 = 0.f, p1 = 0.f, p2 = 0.f, p3 = 0.f;
        for (int idx = tid; idx < 32 * d_w; idx += 256) {
            int c = idx / d_w, h = d_lo + idx - c * d_w;
            float v = C[c * 88 + h];
            int wi = c * 83 + h;
            p0 += v * wf[wi];
            p1 += v * wf[wi + 2656];
            p2 += v * wf[wi + 2 * 2656];
            p3 += v * wf[wi + 3 * 2656];
        }
        #pragma unroll
        for (int off = 16; off; off >>= 1) {
            p0 += __shfl_down_sync(0xffffffffu, p0, off);
            p1 += __shfl_down_sync(0xffffffffu, p1, off);
            p2 += __shfl_down_sync(0xffffffffu, p2, off);
            p3 += __shfl_down_sync(0xffffffffu, p3, off);
        }
        int lane = tid & 31, wid = tid >> 5;
        if (lane == 0) {
            A[wid * 4 + 0] = p0;
            A[wid * 4 + 1] = p1;
            A[wid * 4 + 2] = p2;
            A[wid * 4 + 3] = p3;
        }
    }
    __syncthreads();
    if (tid < 4) {
        float s = (half == 0) ? bf[tid] : 0.0f;   // bias added exactly once
        #pragma unroll
        for (int w = 0; w < 8; ++w) s += A[w * 4 + tid];
        atomicAdd(&out[n * 4 + tid], s);          // 2 commutative adds -> deterministic
    }
}

extern "C" void kernel_launch(void* const* d_in, const int* in_sizes, int n_in,
                              void* d_out, int out_size) {
    const float* x  = (const float*)d_in[0];
    const float* w1 = (const float*)d_in[1];
    const float* b1 = (const float*)d_in[2];
    const float* w2 = (const float*)d_in[3];
    const float* b2 = (const float*)d_in[4];
    const float* w3 = (const float*)d_in[5];
    const float* b3 = (const float*)d_in[6];
    const float* wf = (const float*)d_in[7];
    const float* bf = (const float*)d_in[8];
    float* out = (float*)d_out;

    int n = in_sizes[0] / (180 * 50);   // batch size (256)
    zero_out_kernel<<<(out_size + 255) / 256, 256>>>(out, out_size);
    catnet_kernel<<<2 * n, 256>>>(x, w1, b1, w2, b2, w3, b3, wf, bf, out);
}